// round 10
// baseline (speedup 1.0000x reference)
#include <cuda_runtime.h>
#include <cuda.h>
#include <cstdint>

// Problem constants
#define NUM_USERS 100000
#define NUM_ITEMS 100000
#define EMB_K 6
#define BATCH 2048

#define N4        (NUM_USERS / 4)   // 25000 float4 per row
#define ROWS      8                 // batch rows per block
#define NSPLIT    2                 // column splits
#define THREADS   256
#define COLS4     (N4 / NSPLIT)     // 12500 float4 per split
#define STAGE_C4  256               // float4 columns per stage (= THREADS)
#define NITER     ((COLS4 + STAGE_C4 - 1) / STAGE_C4)   // 49
#define NSTAGE    3
#define STAGE_BYTES (ROWS * STAGE_C4 * 16)              // 32768
#define TMA_BOX_BYTES 8192                              // [256 floats x 8 rows]
#define ROWGROUPS (BATCH / ROWS)          // 256
#define GRID      (ROWGROUPS * NSPLIT)    // 512

// Scratch: partial U_emb per split, completion counter
__device__ float g_Upart[NSPLIT][BATCH][EMB_K];
__device__ unsigned int g_done;

// ---------------- PTX helpers ----------------
__device__ __forceinline__ unsigned smem_u32(const void* p) {
    return (unsigned)__cvta_generic_to_shared(p);
}
__device__ __forceinline__ void mbar_init(unsigned bar, unsigned count) {
    asm volatile("mbarrier.init.shared.b64 [%0], %1;" :: "r"(bar), "r"(count) : "memory");
}
__device__ __forceinline__ void mbar_expect_tx(unsigned bar, unsigned bytes) {
    asm volatile("mbarrier.arrive.expect_tx.shared.b64 _, [%0], %1;"
                 :: "r"(bar), "r"(bytes) : "memory");
}
__device__ __forceinline__ void mbar_arrive(unsigned bar) {
    asm volatile("mbarrier.arrive.shared.b64 _, [%0];" :: "r"(bar) : "memory");
}
__device__ __forceinline__ void mbar_wait(unsigned bar, unsigned phase) {
    asm volatile(
        "{\n\t"
        ".reg .pred P1;\n\t"
        "WAIT_LOOP_%=:\n\t"
        "mbarrier.try_wait.parity.acquire.cta.shared::cta.b64 P1, [%0], %1, 0x989680;\n\t"
        "@P1 bra.uni WAIT_DONE_%=;\n\t"
        "bra.uni WAIT_LOOP_%=;\n\t"
        "WAIT_DONE_%=:\n\t"
        "}"
        :: "r"(bar), "r"(phase) : "memory");
}
__device__ __forceinline__ void mbar_wait_relaxed(unsigned bar, unsigned phase) {
    asm volatile(
        "{\n\t"
        ".reg .pred P1;\n\t"
        "WAIT_LOOP_%=:\n\t"
        "mbarrier.try_wait.parity.relaxed.cta.shared::cta.b64 P1, [%0], %1, 0x989680;\n\t"
        "@P1 bra.uni WAIT_DONE_%=;\n\t"
        "bra.uni WAIT_LOOP_%=;\n\t"
        "WAIT_DONE_%=:\n\t"
        "}"
        :: "r"(bar), "r"(phase) : "memory");
}
__device__ __forceinline__ void tma_load_2d(unsigned dst, const CUtensorMap* map,
                                            int cx, int cy, unsigned bar) {
    asm volatile(
        "cp.async.bulk.tensor.2d.shared::cta.global.tile.mbarrier::complete_tx::bytes "
        "[%0], [%1, {%2, %3}], [%4];"
        :: "r"(dst), "l"(map), "r"(cx), "r"(cy), "r"(bar) : "memory");
}

// ---------------------------------------------------------------------------
// Shared epilogue: last-block election + gather + MLP (device inline)
// ---------------------------------------------------------------------------
__device__ __forceinline__ void epilogue(const void* __restrict__ x_item,
                                         const float* __restrict__ H_w,
                                         const float* __restrict__ W1,
                                         const float* __restrict__ b1,
                                         const float* __restrict__ W2,
                                         const float* __restrict__ b2,
                                         const float* __restrict__ W3,
                                         float* __restrict__ out,
                                         int tid, int grid_blocks) {
    __shared__ int s_last;
    __threadfence();
    __syncthreads();
    if (tid == 0) {
        unsigned int old = atomicAdd(&g_done, 1u);
        s_last = (old == (unsigned)(grid_blocks - 1)) ? 1 : 0;
    }
    __syncthreads();
    if (!s_last) return;

    if (tid == 0) g_done = 0;
    __threadfence();

    __shared__ int s_nz;
    if (tid == 0) s_nz = 0;
    __syncthreads();
    {
        const unsigned int* p = (const unsigned int*)x_item;
        for (int b = tid; b < 1024; b += THREADS)
            if (p[2 * b + 1] != 0u) s_nz = 1;   // benign race
    }

    __shared__ float sW1[16 * 12], sb1[16], sW2[8 * 16], sb2[8], sW3[9];
    if (tid < 16 * 12) sW1[tid] = W1[tid];
    if (tid < 16)      sb1[tid] = b1[tid];
    if (tid < 8 * 16)  sW2[tid] = W2[tid];
    if (tid < 8)       sb2[tid] = b2[tid];
    if (tid < 9)       sW3[tid] = W3[tid];
    __syncthreads();
    const bool is64 = (s_nz == 0);

    for (int b = tid; b < BATCH; b += THREADS) {
        long long idx;
        if (is64) idx = ((const long long*)x_item)[b];
        else      idx = (long long)(((const int*)x_item)[b]);

        float z[12];
#pragma unroll
        for (int k = 0; k < EMB_K; k++) {
            float s = 0.0f;
#pragma unroll
            for (int sp = 0; sp < NSPLIT; sp++)
                s += g_Upart[sp][b][k];
            z[k] = s;
        }
#pragma unroll
        for (int k = 0; k < EMB_K; k++)
            z[EMB_K + k] = __ldg(&H_w[(size_t)k * NUM_ITEMS + idx]);

        float h1[16];
#pragma unroll
        for (int j = 0; j < 16; j++) {
            float s = sb1[j];
#pragma unroll
            for (int i = 0; i < 12; i++)
                s = fmaf(z[i], sW1[j * 12 + i], s);
            h1[j] = fmaxf(s, 0.0f);
        }
        float h2[8];
#pragma unroll
        for (int j = 0; j < 8; j++) {
            float s = sb2[j];
#pragma unroll
            for (int i = 0; i < 16; i++)
                s = fmaf(h1[i], sW2[j * 16 + i], s);
            h2[j] = fmaxf(s, 0.0f);
        }
        float o = sW3[8];
#pragma unroll
        for (int i = 0; i < 8; i++)
            o = fmaf(h2[i], sW3[i], o);
        out[b] = o;
    }
}

// ---------------------------------------------------------------------------
// TMA pipelined kernel
// ---------------------------------------------------------------------------
__global__ __launch_bounds__(THREADS, 2)
void fused_tma_kernel(const __grid_constant__ CUtensorMap tmap,
                      const float4* __restrict__ Ww4,
                      const void*  __restrict__ x_item,
                      const float* __restrict__ H_w,
                      const float* __restrict__ W1, const float* __restrict__ b1,
                      const float* __restrict__ W2, const float* __restrict__ b2,
                      const float* __restrict__ W3,
                      float* __restrict__ out) {
    extern __shared__ __align__(128) float4 xs4[];   // [NSTAGE][2048] float4 = 96KB
    __shared__ __align__(16) unsigned long long mbar[2 * NSTAGE];

    const int tid   = threadIdx.x;
    const int lane  = tid & 31;
    const int warp  = tid >> 5;
    const int bx    = blockIdx.x;
    const int split = bx & (NSPLIT - 1);
    const int rg    = bx >> 1;
    const int row0  = rg * ROWS;
    const int c0    = split * COLS4;           // float4 units
    const int c_end = c0 + COLS4;

    const unsigned full0   = smem_u32(&mbar[0]);       // full[s]  = full0  + 16*s
    const unsigned empty0  = full0 + 8;                // empty[s] = empty0 + 16*s
    const unsigned xs_base = smem_u32(xs4);

    if (tid == 0) {
#pragma unroll
        for (int s = 0; s < NSTAGE; s++) {
            mbar_init(full0 + 16 * s, 1);
            mbar_init(empty0 + 16 * s, THREADS);
        }
        asm volatile("fence.proxy.async.shared::cta;" ::: "memory");
    }
    __syncthreads();

    // Producer cursor (tid 0): phase starts 1 so first empty-waits pass.
    int pstage = 0, pphase = 1;
    // Consumer cursor (all threads): phase starts 0.
    int cstage = 0, cphase = 0;

    // ---------------- prologue: produce stages 0..NSTAGE-2 ----------------
    if (tid == 0) {
#pragma unroll
        for (int n = 0; n < NSTAGE - 1; n++) {
            mbar_wait_relaxed(empty0 + 16 * pstage, pphase);
            const unsigned fb = full0 + 16 * pstage;
            mbar_expect_tx(fb, STAGE_BYTES);
            const int colf = (c0 + n * STAGE_C4) * 4;   // float units
            const unsigned dst = xs_base + pstage * STAGE_BYTES;
#pragma unroll
            for (int q = 0; q < 4; q++)
                tma_load_2d(dst + q * TMA_BOX_BYTES, &tmap, colf + q * 256, row0, fb);
            if (++pstage == NSTAGE) { pstage = 0; pphase ^= 1; }
        }
    }

    float acc[ROWS][EMB_K];
#pragma unroll
    for (int r = 0; r < ROWS; r++)
#pragma unroll
        for (int k = 0; k < EMB_K; k++)
            acc[r][k] = 0.0f;

    // Thread -> (quarter-box, local col) mapping within a stage
    const int q  = tid >> 6;
    const int lc = tid & 63;
    const int xoff4 = q * 512 + lc;            // float4 units; + r*64 per row

    // ---------------- pipelined mainloop ----------------
    for (int j = 0; j < NITER; j++) {
        // produce stage j + NSTAGE-1 (tid 0)
        if (tid == 0 && j + (NSTAGE - 1) < NITER) {
            const int n = j + (NSTAGE - 1);
            mbar_wait_relaxed(empty0 + 16 * pstage, pphase);
            const unsigned fb = full0 + 16 * pstage;
            mbar_expect_tx(fb, STAGE_BYTES);
            const int colf = (c0 + n * STAGE_C4) * 4;
            const unsigned dst = xs_base + pstage * STAGE_BYTES;
#pragma unroll
            for (int qq = 0; qq < 4; qq++)
                tma_load_2d(dst + qq * TMA_BOX_BYTES, &tmap, colf + qq * 256, row0, fb);
            if (++pstage == NSTAGE) { pstage = 0; pphase ^= 1; }
        }

        // consume stage j
        mbar_wait(full0 + 16 * cstage, cphase);

        const int col4 = c0 + j * STAGE_C4 + tid;
        if (col4 < c_end) {
            float4 w[EMB_K];
#pragma unroll
            for (int k = 0; k < EMB_K; k++)
                w[k] = __ldg(Ww4 + (size_t)k * N4 + col4);

            const float4* xstage = xs4 + cstage * (STAGE_BYTES / 16) + xoff4;
#pragma unroll
            for (int r = 0; r < ROWS; r++) {
                const float4 x = xstage[r * 64];
#pragma unroll
                for (int k = 0; k < EMB_K; k++) {
                    acc[r][k] = fmaf(x.x, w[k].x, acc[r][k]);
                    acc[r][k] = fmaf(x.y, w[k].y, acc[r][k]);
                    acc[r][k] = fmaf(x.z, w[k].z, acc[r][k]);
                    acc[r][k] = fmaf(x.w, w[k].w, acc[r][k]);
                }
            }
        }

        mbar_arrive(empty0 + 16 * cstage);
        if (++cstage == NSTAGE) { cstage = 0; cphase ^= 1; }
    }

    // ---------------- block reduction -> partial U_emb ----------------
    __shared__ float sred[THREADS / 32][ROWS * EMB_K];
#pragma unroll
    for (int r = 0; r < ROWS; r++) {
#pragma unroll
        for (int k = 0; k < EMB_K; k++) {
            float v = acc[r][k];
#pragma unroll
            for (int off = 16; off > 0; off >>= 1)
                v += __shfl_down_sync(0xffffffffu, v, off);
            if (lane == 0) sred[warp][r * EMB_K + k] = v;
        }
    }
    __syncthreads();

    if (tid < ROWS * EMB_K) {
        float s = 0.0f;
#pragma unroll
        for (int w2 = 0; w2 < THREADS / 32; w2++)
            s += sred[w2][tid];
        g_Upart[split][row0 + tid / EMB_K][tid % EMB_K] = s;
    }

    epilogue(x_item, H_w, W1, b1, W2, b2, W3, out, tid, GRID);
}

// ---------------------------------------------------------------------------
// Fallback: R3-style LDG kernel (proven 157.7us) if tensor-map encode fails
// ---------------------------------------------------------------------------
__global__ __launch_bounds__(THREADS, 2)
void fused_ldg_kernel(const float4* __restrict__ x_user4,
                      const float4* __restrict__ Ww4,
                      const void*  __restrict__ x_item,
                      const float* __restrict__ H_w,
                      const float* __restrict__ W1, const float* __restrict__ b1,
                      const float* __restrict__ W2, const float* __restrict__ b2,
                      const float* __restrict__ W3,
                      float* __restrict__ out) {
    const int tid   = threadIdx.x;
    const int bx    = blockIdx.x;
    const int split = bx & (NSPLIT - 1);
    const int rg    = bx >> 1;
    const int row0  = rg * ROWS;
    const int c0    = split * COLS4;
    const int c1    = c0 + COLS4;

    float acc[ROWS][EMB_K];
#pragma unroll
    for (int r = 0; r < ROWS; r++)
#pragma unroll
        for (int k = 0; k < EMB_K; k++)
            acc[r][k] = 0.0f;

    for (int i4 = c0 + tid; i4 < c1; i4 += THREADS) {
        float4 w[EMB_K];
#pragma unroll
        for (int k = 0; k < EMB_K; k++)
            w[k] = __ldg(&Ww4[k * N4 + i4]);
#pragma unroll
        for (int r = 0; r < ROWS; r++) {
            const float4 x = __ldg(&x_user4[(size_t)(row0 + r) * N4 + i4]);
#pragma unroll
            for (int k = 0; k < EMB_K; k++) {
                acc[r][k] = fmaf(x.x, w[k].x, acc[r][k]);
                acc[r][k] = fmaf(x.y, w[k].y, acc[r][k]);
                acc[r][k] = fmaf(x.z, w[k].z, acc[r][k]);
                acc[r][k] = fmaf(x.w, w[k].w, acc[r][k]);
            }
        }
    }

    __shared__ float sred[THREADS / 32][ROWS * EMB_K];
    const int lane = tid & 31;
    const int warp = tid >> 5;
#pragma unroll
    for (int r = 0; r < ROWS; r++) {
#pragma unroll
        for (int k = 0; k < EMB_K; k++) {
            float v = acc[r][k];
#pragma unroll
            for (int off = 16; off > 0; off >>= 1)
                v += __shfl_down_sync(0xffffffffu, v, off);
            if (lane == 0) sred[warp][r * EMB_K + k] = v;
        }
    }
    __syncthreads();
    if (tid < ROWS * EMB_K) {
        float s = 0.0f;
#pragma unroll
        for (int w2 = 0; w2 < THREADS / 32; w2++)
            s += sred[w2][tid];
        g_Upart[split][row0 + tid / EMB_K][tid % EMB_K] = s;
    }

    epilogue(x_item, H_w, W1, b1, W2, b2, W3, out, tid, GRID);
}

// ---------------------------------------------------------------------------
// Host launch
// ---------------------------------------------------------------------------
typedef CUresult (*EncodeTiledFn)(
    CUtensorMap*, CUtensorMapDataType, cuuint32_t, void*,
    const cuuint64_t*, const cuuint64_t*, const cuuint32_t*, const cuuint32_t*,
    CUtensorMapInterleave, CUtensorMapSwizzle, CUtensorMapL2promotion,
    CUtensorMapFloatOOBfill);

extern "C" void kernel_launch(void* const* d_in, const int* in_sizes, int n_in,
                              void* d_out, int out_size) {
    const float* x_user = (const float*)d_in[0];
    const void*  x_item = d_in[1];
    const float* W_w    = (const float*)d_in[2];
    const float* H_w    = (const float*)d_in[3];
    const float* W1     = (const float*)d_in[4];
    const float* b1     = (const float*)d_in[5];
    const float* W2     = (const float*)d_in[6];
    const float* b2     = (const float*)d_in[7];
    const float* W3     = (const float*)d_in[8];
    float* out          = (float*)d_out;

    static EncodeTiledFn encode_fn = nullptr;
    static bool probed = false;
    if (!probed) {
        cudaDriverEntryPointQueryResult st;
        void* fp = nullptr;
        cudaError_t e = cudaGetDriverEntryPoint("cuTensorMapEncodeTiled", &fp,
                                                cudaEnableDefault, &st);
        if (e == cudaSuccess && st == cudaDriverEntryPointSuccess)
            encode_fn = (EncodeTiledFn)fp;
        probed = true;
    }

    bool tma_ok = false;
    CUtensorMap tmap;
    if (encode_fn) {
        cuuint64_t dims[2]    = {NUM_USERS, BATCH};
        cuuint64_t strides[1] = {(cuuint64_t)NUM_USERS * sizeof(float)};
        cuuint32_t box[2]     = {256, ROWS};
        cuuint32_t estr[2]    = {1, 1};
        CUresult r = encode_fn(&tmap, CU_TENSOR_MAP_DATA_TYPE_FLOAT32, 2,
                               (void*)x_user, dims, strides, box, estr,
                               CU_TENSOR_MAP_INTERLEAVE_NONE,
                               CU_TENSOR_MAP_SWIZZLE_NONE,
                               CU_TENSOR_MAP_L2_PROMOTION_L2_128B,
                               CU_TENSOR_MAP_FLOAT_OOB_FILL_NONE);
        tma_ok = (r == CUDA_SUCCESS);
    }

    if (tma_ok) {
        const int dyn_smem = NSTAGE * STAGE_BYTES;   // 96 KB
        static bool attr_set = false;
        if (!attr_set) {
            cudaFuncSetAttribute(fused_tma_kernel,
                                 cudaFuncAttributeMaxDynamicSharedMemorySize,
                                 dyn_smem);
            attr_set = true;
        }
        fused_tma_kernel<<<GRID, THREADS, dyn_smem>>>(
            tmap, (const float4*)W_w, x_item, H_w, W1, b1, W2, b2, W3, out);
    } else {
        fused_ldg_kernel<<<GRID, THREADS>>>(
            (const float4*)x_user, (const float4*)W_w, x_item, H_w,
            W1, b1, W2, b2, W3, out);
    }
}

// round 11
// speedup vs baseline: 1.1391x; 1.1391x over previous
#include <cuda_runtime.h>
#include <cstdint>

// Problem constants
#define NUM_USERS 100000
#define NUM_ITEMS 100000
#define EMB_K 6
#define BATCH 2048

#define N4      (NUM_USERS / 4)   // 25000 float4 per row
#define ROWS    8                 // batch rows per block
#define NSPLIT  2                 // column splits
#define THREADS 256
#define COLS4   (N4 / NSPLIT)     // 12500 float4 per split
#define NMAIN   (COLS4 / THREADS) // 48 full iterations (12288 cols)
#define NTAIL   (COLS4 - NMAIN * THREADS)  // 212
#define ROWGROUPS (BATCH / ROWS)          // 256
#define GRID      (ROWGROUPS * NSPLIT)    // 512

// Scratch: partial U_emb per split, completion counter
__device__ float g_Upart[NSPLIT][BATCH][EMB_K];
__device__ unsigned int g_done;

__global__ __launch_bounds__(THREADS, 2)   // 128-reg cap -> 2 blocks/SM
void fused_kernel(const float4* __restrict__ x_user4,
                  const float4* __restrict__ Ww4,
                  const void*  __restrict__ x_item,
                  const float* __restrict__ H_w,
                  const float* __restrict__ W1, const float* __restrict__ b1,
                  const float* __restrict__ W2, const float* __restrict__ b2,
                  const float* __restrict__ W3,
                  float* __restrict__ out) {
    const int tid   = threadIdx.x;
    const int lane  = tid & 31;
    const int warp  = tid >> 5;
    const int bx    = blockIdx.x;
    const int split = bx & (NSPLIT - 1);
    const int rg    = bx >> 1;
    const int row0  = rg * ROWS;
    const int c0    = split * COLS4;
    const int c1    = c0 + COLS4;

    // Row base pointers
    const float4* xrow[ROWS];
#pragma unroll
    for (int r = 0; r < ROWS; r++)
        xrow[r] = x_user4 + (size_t)(row0 + r) * N4;

    float acc[ROWS][EMB_K];
#pragma unroll
    for (int r = 0; r < ROWS; r++)
#pragma unroll
        for (int k = 0; k < EMB_K; k++)
            acc[r][k] = 0.0f;

    // ---------------- software-pipelined mainloop ----------------
    // Rotating register buffer xr[] holds iteration j's x values; while the
    // FMA block for iteration j runs, loads for j+1 are already in flight.
    int col = c0 + tid;
    float4 xr[ROWS];
#pragma unroll
    for (int r = 0; r < ROWS; r++)
        xr[r] = __ldg(xrow[r] + col);

    for (int j = 0; j < NMAIN; j++) {
        // prefetch column for iter j+1 (clamped: last main iter may run past
        // c1 for some threads; re-load a safe column instead, value unused
        // by main loop and overwritten semantics handled by tail guard)
        const int ncol = col + THREADS;
        const int pcol = (ncol < c1) ? ncol : (c0 + tid);

        float4 w[EMB_K];
#pragma unroll
        for (int k = 0; k < EMB_K; k++)
            w[k] = __ldg(Ww4 + (size_t)k * N4 + col);

#pragma unroll
        for (int r = 0; r < ROWS; r++) {
            const float4 x = xr[r];
            xr[r] = __ldg(xrow[r] + pcol);   // prefetch next iter, same reg
#pragma unroll
            for (int k = 0; k < EMB_K; k++) {
                acc[r][k] = fmaf(x.x, w[k].x, acc[r][k]);
                acc[r][k] = fmaf(x.y, w[k].y, acc[r][k]);
                acc[r][k] = fmaf(x.z, w[k].z, acc[r][k]);
                acc[r][k] = fmaf(x.w, w[k].w, acc[r][k]);
            }
        }
        col = ncol;
    }

    // ---------------- tail iteration (cols 12288..12499 of the split) ------
    // xr[] already holds this column's values for threads with col < c1.
    if (col < c1) {
        float4 w[EMB_K];
#pragma unroll
        for (int k = 0; k < EMB_K; k++)
            w[k] = __ldg(Ww4 + (size_t)k * N4 + col);
#pragma unroll
        for (int r = 0; r < ROWS; r++) {
            const float4 x = xr[r];
#pragma unroll
            for (int k = 0; k < EMB_K; k++) {
                acc[r][k] = fmaf(x.x, w[k].x, acc[r][k]);
                acc[r][k] = fmaf(x.y, w[k].y, acc[r][k]);
                acc[r][k] = fmaf(x.z, w[k].z, acc[r][k]);
                acc[r][k] = fmaf(x.w, w[k].w, acc[r][k]);
            }
        }
    }

    // ---------------- block reduction -> partial U_emb ----------------
    __shared__ float sred[THREADS / 32][ROWS * EMB_K];   // 8 x 48 floats

#pragma unroll
    for (int r = 0; r < ROWS; r++) {
#pragma unroll
        for (int k = 0; k < EMB_K; k++) {
            float v = acc[r][k];
#pragma unroll
            for (int off = 16; off > 0; off >>= 1)
                v += __shfl_down_sync(0xffffffffu, v, off);
            if (lane == 0) sred[warp][r * EMB_K + k] = v;
        }
    }
    __syncthreads();

    if (tid < ROWS * EMB_K) {
        float s = 0.0f;
#pragma unroll
        for (int w2 = 0; w2 < THREADS / 32; w2++)
            s += sred[w2][tid];
        g_Upart[split][row0 + tid / EMB_K][tid % EMB_K] = s;
    }

    // ---------------- last-block election ----------------
    __shared__ int s_last;
    __threadfence();                 // publish partials
    __syncthreads();
    if (tid == 0) {
        unsigned int old = atomicAdd(&g_done, 1u);
        s_last = (old == GRID - 1) ? 1 : 0;
    }
    __syncthreads();
    if (!s_last) return;

    if (tid == 0) g_done = 0;        // reset for next graph replay
    __threadfence();

    // ---------------- int64/int32 index detection ----------------
    __shared__ int s_nz;
    if (tid == 0) s_nz = 0;
    __syncthreads();
    {
        const unsigned int* p = (const unsigned int*)x_item;
        for (int b = tid; b < 1024; b += THREADS)
            if (p[2 * b + 1] != 0u) s_nz = 1;   // benign race
    }

    // ---------------- tiny MLP weights into smem ----------------
    __shared__ float sW1[16 * 12], sb1[16], sW2[8 * 16], sb2[8], sW3[9];
    if (tid < 16 * 12) sW1[tid] = W1[tid];
    if (tid < 16)      sb1[tid] = b1[tid];
    if (tid < 8 * 16)  sW2[tid] = W2[tid];
    if (tid < 8)       sb2[tid] = b2[tid];
    if (tid < 9)       sW3[tid] = W3[tid];
    __syncthreads();
    const bool is64 = (s_nz == 0);

    // ---------------- gather + MLP for all BATCH elements ----------------
    for (int b = tid; b < BATCH; b += THREADS) {
        long long idx;
        if (is64) idx = ((const long long*)x_item)[b];
        else      idx = (long long)(((const int*)x_item)[b]);

        float z[12];
#pragma unroll
        for (int k = 0; k < EMB_K; k++) {
            float s = 0.0f;
#pragma unroll
            for (int sp = 0; sp < NSPLIT; sp++)
                s += g_Upart[sp][b][k];
            z[k] = s;
        }
#pragma unroll
        for (int k = 0; k < EMB_K; k++)
            z[EMB_K + k] = __ldg(&H_w[(size_t)k * NUM_ITEMS + idx]);

        float h1[16];
#pragma unroll
        for (int j = 0; j < 16; j++) {
            float s = sb1[j];
#pragma unroll
            for (int i = 0; i < 12; i++)
                s = fmaf(z[i], sW1[j * 12 + i], s);
            h1[j] = fmaxf(s, 0.0f);
        }

        float h2[8];
#pragma unroll
        for (int j = 0; j < 8; j++) {
            float s = sb2[j];
#pragma unroll
            for (int i = 0; i < 16; i++)
                s = fmaf(h1[i], sW2[j * 16 + i], s);
            h2[j] = fmaxf(s, 0.0f);
        }

        float o = sW3[8];   // ones-column term
#pragma unroll
        for (int i = 0; i < 8; i++)
            o = fmaf(h2[i], sW3[i], o);

        out[b] = o;
    }
}

extern "C" void kernel_launch(void* const* d_in, const int* in_sizes, int n_in,
                              void* d_out, int out_size) {
    const float* x_user = (const float*)d_in[0];
    const void*  x_item = d_in[1];
    const float* W_w    = (const float*)d_in[2];
    const float* H_w    = (const float*)d_in[3];
    const float* W1     = (const float*)d_in[4];
    const float* b1     = (const float*)d_in[5];
    const float* W2     = (const float*)d_in[6];
    const float* b2     = (const float*)d_in[7];
    const float* W3     = (const float*)d_in[8];
    float* out          = (float*)d_out;

    fused_kernel<<<GRID, THREADS>>>(
        (const float4*)x_user, (const float4*)W_w, x_item, H_w,
        W1, b1, W2, b2, W3, out);
}

// round 12
// speedup vs baseline: 1.3130x; 1.1527x over previous
#include <cuda_runtime.h>
#include <cstdint>

// Problem constants
#define NUM_USERS 100000
#define NUM_ITEMS 100000
#define EMB_K 6
#define BATCH 2048

#define N4      (NUM_USERS / 4)   // 25000 float4 per row
#define ROWS    8                 // batch rows per block (R3's proven shape)
#define NSPLIT  8                 // column splits: TLB-locality knob
#define THREADS 256
#define COLS4   (N4 / NSPLIT)     // 3125 float4 per split
#define ROWGROUPS (BATCH / ROWS)          // 256
#define GRID      (ROWGROUPS * NSPLIT)    // 2048

// Scratch: partial U_emb per split, completion counter
__device__ float g_Upart[NSPLIT][BATCH][EMB_K];
__device__ unsigned int g_done;

__global__ __launch_bounds__(THREADS, 2)   // cap regs at 128 -> 2 blocks/SM
void fused_kernel(const float4* __restrict__ x_user4,
                  const float4* __restrict__ Ww4,
                  const void*  __restrict__ x_item,
                  const float* __restrict__ H_w,
                  const float* __restrict__ W1, const float* __restrict__ b1,
                  const float* __restrict__ W2, const float* __restrict__ b2,
                  const float* __restrict__ W3,
                  float* __restrict__ out) {
    const int tid   = threadIdx.x;
    const int bx    = blockIdx.x;
    // Consecutive bids share a rowgroup -> resident wave covers few rowgroups
    // -> active TLB page set (~3 pages per rowgroup) fits in 128 entries.
    const int split = bx & (NSPLIT - 1);
    const int rg    = bx >> 3;              // log2(NSPLIT)
    const int row0  = rg * ROWS;
    const int c0    = split * COLS4;
    const int c1    = c0 + COLS4;

    // ---------------- streaming GEMV (R3's proven inner loop) ----------------
    float acc[ROWS][EMB_K];
#pragma unroll
    for (int r = 0; r < ROWS; r++)
#pragma unroll
        for (int k = 0; k < EMB_K; k++)
            acc[r][k] = 0.0f;

    for (int i4 = c0 + tid; i4 < c1; i4 += THREADS) {
        float4 w[EMB_K];
#pragma unroll
        for (int k = 0; k < EMB_K; k++)
            w[k] = __ldg(&Ww4[k * N4 + i4]);

#pragma unroll
        for (int r = 0; r < ROWS; r++) {
            const float4 x = __ldg(&x_user4[(size_t)(row0 + r) * N4 + i4]);
#pragma unroll
            for (int k = 0; k < EMB_K; k++) {
                acc[r][k] = fmaf(x.x, w[k].x, acc[r][k]);
                acc[r][k] = fmaf(x.y, w[k].y, acc[r][k]);
                acc[r][k] = fmaf(x.z, w[k].z, acc[r][k]);
                acc[r][k] = fmaf(x.w, w[k].w, acc[r][k]);
            }
        }
    }

    // ---------------- block reduction -> partial U_emb ----------------
    __shared__ float sred[THREADS / 32][ROWS * EMB_K];   // 8 x 48 floats
    const int lane = tid & 31;
    const int warp = tid >> 5;

#pragma unroll
    for (int r = 0; r < ROWS; r++) {
#pragma unroll
        for (int k = 0; k < EMB_K; k++) {
            float v = acc[r][k];
#pragma unroll
            for (int off = 16; off > 0; off >>= 1)
                v += __shfl_down_sync(0xffffffffu, v, off);
            if (lane == 0) sred[warp][r * EMB_K + k] = v;
        }
    }
    __syncthreads();

    if (tid < ROWS * EMB_K) {
        float s = 0.0f;
#pragma unroll
        for (int w2 = 0; w2 < THREADS / 32; w2++)
            s += sred[w2][tid];
        g_Upart[split][row0 + tid / EMB_K][tid % EMB_K] = s;
    }

    // ---------------- last-block election ----------------
    __shared__ int s_last;
    __threadfence();                 // publish partials
    __syncthreads();
    if (tid == 0) {
        unsigned int old = atomicAdd(&g_done, 1u);
        s_last = (old == GRID - 1) ? 1 : 0;
    }
    __syncthreads();
    if (!s_last) return;

    // We are the last block: all partials are visible.
    if (tid == 0) g_done = 0;        // reset for next graph replay
    __threadfence();

    // ---------------- int64/int32 index detection ----------------
    __shared__ int s_nz;
    if (tid == 0) s_nz = 0;
    __syncthreads();
    {
        const unsigned int* p = (const unsigned int*)x_item;
        for (int b = tid; b < 1024; b += THREADS)
            if (p[2 * b + 1] != 0u) s_nz = 1;   // benign race
    }

    // ---------------- tiny MLP weights into smem ----------------
    __shared__ float sW1[16 * 12], sb1[16], sW2[8 * 16], sb2[8], sW3[9];
    if (tid < 16 * 12) sW1[tid] = W1[tid];
    if (tid < 16)      sb1[tid] = b1[tid];
    if (tid < 8 * 16)  sW2[tid] = W2[tid];
    if (tid < 8)       sb2[tid] = b2[tid];
    if (tid < 9)       sW3[tid] = W3[tid];
    __syncthreads();
    const bool is64 = (s_nz == 0);

    // ---------------- gather + MLP for all BATCH elements ----------------
    for (int b = tid; b < BATCH; b += THREADS) {
        long long idx;
        if (is64) idx = ((const long long*)x_item)[b];
        else      idx = (long long)(((const int*)x_item)[b]);

        float z[12];
#pragma unroll
        for (int k = 0; k < EMB_K; k++) {
            float s = 0.0f;
#pragma unroll
            for (int sp = 0; sp < NSPLIT; sp++)
                s += g_Upart[sp][b][k];
            z[k] = s;
        }
#pragma unroll
        for (int k = 0; k < EMB_K; k++)
            z[EMB_K + k] = __ldg(&H_w[(size_t)k * NUM_ITEMS + idx]);

        float h1[16];
#pragma unroll
        for (int j = 0; j < 16; j++) {
            float s = sb1[j];
#pragma unroll
            for (int i = 0; i < 12; i++)
                s = fmaf(z[i], sW1[j * 12 + i], s);
            h1[j] = fmaxf(s, 0.0f);
        }

        float h2[8];
#pragma unroll
        for (int j = 0; j < 8; j++) {
            float s = sb2[j];
#pragma unroll
            for (int i = 0; i < 16; i++)
                s = fmaf(h1[i], sW2[j * 16 + i], s);
            h2[j] = fmaxf(s, 0.0f);
        }

        float o = sW3[8];   // ones-column term
#pragma unroll
        for (int i = 0; i < 8; i++)
            o = fmaf(h2[i], sW3[i], o);

        out[b] = o;
    }
}

extern "C" void kernel_launch(void* const* d_in, const int* in_sizes, int n_in,
                              void* d_out, int out_size) {
    const float* x_user = (const float*)d_in[0];
    const void*  x_item = d_in[1];
    const float* W_w    = (const float*)d_in[2];
    const float* H_w    = (const float*)d_in[3];
    const float* W1     = (const float*)d_in[4];
    const float* b1     = (const float*)d_in[5];
    const float* W2     = (const float*)d_in[6];
    const float* b2     = (const float*)d_in[7];
    const float* W3     = (const float*)d_in[8];
    float* out          = (float*)d_out;

    fused_kernel<<<GRID, THREADS>>>(
        (const float4*)x_user, (const float4*)W_w, x_item, H_w,
        W1, b1, W2, b2, W3, out);
}